// round 17
// baseline (speedup 1.0000x reference)
#include <cuda_runtime.h>
#include <cuda_bf16.h>
#include <math.h>

#define BB 2
#define SS 2048
#define EE 768
#define HH 12
#define DK 64

// Packed bf16x2 hi/lo interchange buffers (allocation-free)
__device__ unsigned g_Qh[BB*HH*SS*32], g_Ql[BB*HH*SS*32];  // [bhs][dk2], pre-scaled 1/8
__device__ unsigned g_Kh[BB*HH*SS*32], g_Kl[BB*HH*SS*32];  // [bhs][dk2]
__device__ unsigned g_Vh[BB*HH*SS*32], g_Vl[BB*HH*SS*32];  // [bhs][dk2]
__device__ unsigned g_Ch[BB*SS*384],  g_Cl[BB*SS*384];     // concat [m][e2]

__device__ __forceinline__ void split2(float x0, float x1, unsigned& hi, unsigned& lo) {
    __nv_bfloat162 h2 = __floats2bfloat162_rn(x0, x1);
    float h0 = __bfloat162float(__low2bfloat16(h2));
    float h1 = __bfloat162float(__high2bfloat16(h2));
    __nv_bfloat162 l2 = __floats2bfloat162_rn(x0 - h0, x1 - h1);
    hi = *reinterpret_cast<unsigned*>(&h2);
    lo = *reinterpret_cast<unsigned*>(&l2);
}

__device__ __forceinline__ void mma16(float c[4], const unsigned a[4], const unsigned* b) {
    asm volatile(
        "mma.sync.aligned.m16n8k16.row.col.f32.bf16.bf16.f32 "
        "{%0,%1,%2,%3},{%4,%5,%6,%7},{%8,%9},{%0,%1,%2,%3};"
        : "+f"(c[0]), "+f"(c[1]), "+f"(c[2]), "+f"(c[3])
        : "r"(a[0]), "r"(a[1]), "r"(a[2]), "r"(a[3]), "r"(b[0]), "r"(b[1]));
}

__device__ __forceinline__ void ldsm_x4(unsigned r[4], const void* p) {
    unsigned addr = (unsigned)__cvta_generic_to_shared(p);
    asm volatile("ldmatrix.sync.aligned.m8n8.x4.shared.b16 {%0,%1,%2,%3}, [%4];"
                 : "=r"(r[0]), "=r"(r[1]), "=r"(r[2]), "=r"(r[3]) : "r"(addr));
}

__device__ __forceinline__ void ldsm_x4_trans(unsigned r[4], const void* p) {
    unsigned addr = (unsigned)__cvta_generic_to_shared(p);
    asm volatile("ldmatrix.sync.aligned.m8n8.x4.trans.shared.b16 {%0,%1,%2,%3}, [%4];"
                 : "=r"(r[0]), "=r"(r[1]), "=r"(r[2]), "=r"(r[3]) : "r"(addr));
}

#define GW 20

// ---------------------------------------------------------------------------
// Fused QKV GEMM: X[4096,768] @ Wall[768,2304], 128x128 tiles, 512 threads
// (16 warps: 8 M-groups x 2 N-halves), register-prefetch pipelined.
// grid=(32,18). Epilogue -> packed hi/lo Q(x1/8)/K/V.
// ---------------------------------------------------------------------------
__global__ __launch_bounds__(512) void qkv_gemm_kernel(
    const float* __restrict__ Xq, const float* __restrict__ Xk, const float* __restrict__ Xv,
    const float* __restrict__ Wq, const float* __restrict__ Wk, const float* __restrict__ Wv)
{
    __shared__ unsigned Ah[128*GW], Al[128*GW];   // [row][k2]
    __shared__ unsigned Bh[128*GW], Bl[128*GW];   // [n][k2]

    int bx = blockIdx.x, by = blockIdx.y;
    int t = threadIdx.x, w = t >> 5, l = t & 31;
    int wm = w >> 1;                 // M group: rows [16*wm, 16*wm+16)
    int wn = w & 1;                  // N half: cols [64*wn, 64*wn+64)
    int t4 = l & 3;
    int g = l >> 2;
    int lj = l >> 3, lr = l & 7;
    int m0 = bx * 128;
    int n0 = by * 128;

    int which = n0 / EE;
    int rem = n0 - which * EE;
    const float* A  = (which == 0) ? Xq : (which == 1) ? Xk : Xv;
    const float* Ws = (which == 0) ? Wq : (which == 1) ? Wk : Wv;
    const float* Bbase = Ws + (size_t)(rem / 64) * EE * DK;

    float acc[8][4] = {};
    int r0 = 16*wm + g;

    int arow = 16*wm + lr + (lj & 1) * 8;
    int acol_q = (lj >> 1) * 4;
    int brow_off = lr + (lj >> 1) * 8;
    int bcol_q = (lj & 1) * 4;

    // staging: A rows ar + i*32 (i<4), B k2 = bk2 + i*4 (i<4)
    int ar = t >> 4, ak2 = t & 15;
    int bn = t & 127, bk2 = t >> 7;
    int hsel = bn >> 6;
    size_t bcol_off = (size_t)hsel * EE * DK + (bn & 63);

    float2 pa[4];
    float  pb0[4], pb1[4];

    #pragma unroll
    for (int i = 0; i < 4; i++)
        pa[i] = *(const float2*)&A[(size_t)(m0 + ar + i*32) * EE + 2*ak2];
    #pragma unroll
    for (int i = 0; i < 4; i++) {
        pb0[i] = Bbase[(size_t)(2*(bk2 + i*4))     * DK + bcol_off];
        pb1[i] = Bbase[(size_t)(2*(bk2 + i*4) + 1) * DK + bcol_off];
    }

    for (int k0 = 0; k0 < EE; k0 += 32) {
        __syncthreads();
        #pragma unroll
        for (int i = 0; i < 4; i++)
            split2(pa[i].x, pa[i].y, Ah[(ar + i*32)*GW + ak2], Al[(ar + i*32)*GW + ak2]);
        #pragma unroll
        for (int i = 0; i < 4; i++)
            split2(pb0[i], pb1[i], Bh[bn*GW + bk2 + i*4], Bl[bn*GW + bk2 + i*4]);
        __syncthreads();

        if (k0 + 32 < EE) {
            int kn = k0 + 32;
            #pragma unroll
            for (int i = 0; i < 4; i++)
                pa[i] = *(const float2*)&A[(size_t)(m0 + ar + i*32) * EE + kn + 2*ak2];
            #pragma unroll
            for (int i = 0; i < 4; i++) {
                pb0[i] = Bbase[(size_t)(kn + 2*(bk2 + i*4))     * DK + bcol_off];
                pb1[i] = Bbase[(size_t)(kn + 2*(bk2 + i*4) + 1) * DK + bcol_off];
            }
        }

        #pragma unroll
        for (int kc = 0; kc < 2; kc++) {
            unsigned ah[4], al[4];
            ldsm_x4(ah, &Ah[arow*GW + kc*8 + acol_q]);
            ldsm_x4(al, &Al[arow*GW + kc*8 + acol_q]);
            #pragma unroll
            for (int n0p = 0; n0p < 4; n0p++) {
                unsigned bh[4], bl[4];
                int br = (wn*64 + n0p*16 + brow_off)*GW + kc*8 + bcol_q;
                ldsm_x4(bh, &Bh[br]);
                ldsm_x4(bl, &Bl[br]);
                mma16(acc[2*n0p],   ah, bh);
                mma16(acc[2*n0p],   ah, bl);
                mma16(acc[2*n0p],   al, bh);
                mma16(acc[2*n0p+1], ah, bh+2);
                mma16(acc[2*n0p+1], ah, bl+2);
                mma16(acc[2*n0p+1], al, bh+2);
            }
        }
    }

    unsigned* Gh = (which == 0) ? g_Qh : (which == 1) ? g_Kh : g_Vh;
    unsigned* Gl = (which == 0) ? g_Ql : (which == 1) ? g_Kl : g_Vl;
    float sc = (which == 0) ? 0.125f : 1.0f;

    int rg1 = m0 + r0, rg2 = rg1 + 8;
    int b1 = rg1 >> 11, s1 = rg1 & 2047;
    int b2 = rg2 >> 11, s2 = rg2 & 2047;
    #pragma unroll
    for (int nb = 0; nb < 8; nb++) {
        int nloc = wn*64 + nb*8 + 2*t4;
        int head = (rem + nloc) >> 6;
        int wd = (nloc & 63) >> 1;
        size_t p1 = ((size_t)(b1*HH + head)*SS + s1) * 32 + wd;
        size_t p2 = ((size_t)(b2*HH + head)*SS + s2) * 32 + wd;
        unsigned hi, lo;
        split2(acc[nb][0]*sc, acc[nb][1]*sc, hi, lo);
        Gh[p1] = hi; Gl[p1] = lo;
        split2(acc[nb][2]*sc, acc[nb][3]*sc, hi, lo);
        Gh[p2] = hi; Gl[p2] = lo;
    }
}

// ---------------------------------------------------------------------------
// Flash attention (R13-proven): 3xBF16, register softmax, copy staging,
// ldmatrix.trans V. grid=(S/128, H, B), block=256. Smem 36.9KB -> 2 CTAs/SM.
// ---------------------------------------------------------------------------
#define KW 36
#define QR 128

__global__ __launch_bounds__(256, 2) void flash_kernel(const int* __restrict__ mask)
{
    __shared__ unsigned SB[4*64*KW];            // Kh | Kl | Vh | Vl
    unsigned* Kh = SB;
    unsigned* Kl = SB + 64*KW;
    unsigned* Vh = SB + 2*64*KW;                // [key][dk2]
    unsigned* Vl = SB + 3*64*KW;

    int qt = blockIdx.x, h = blockIdx.y, b = blockIdx.z;
    int t = threadIdx.x, w = t >> 5, l = t & 31;
    int t4 = l & 3;
    int g = l >> 2;
    int lj = l >> 3, lr = l & 7;
    int r0 = 16*w + g;

    size_t qbase = ((size_t)(b*HH + h)*SS + qt*QR) * 32;
    size_t kvbase = (size_t)(b*HH + h) * SS * 32;
    const int* Mp = mask + ((size_t)b*SS + qt*QR) * SS;

    int arow = 16*w + lr + (lj & 1) * 8;
    int acol_q = (lj >> 1) * 4;
    int brow_off = lr + (lj >> 1) * 8;
    int bcol_q = (lj & 1) * 4;
    int vrow_off = (lj & 1) * 8 + lr;
    int vcol_q = (lj >> 1) * 4;

    // Stage Q words (K area then V area as scratch), pull fragments to regs.
    #pragma unroll
    for (int i = 0; i < 16; i++) {
        int idx = t + i * 256;
        int r = idx >> 5, k2 = idx & 31;
        SB[r*KW + k2]           = g_Qh[qbase + r*32 + k2];
        SB[QR*KW + r*KW + k2]   = g_Ql[qbase + r*32 + k2];
    }
    __syncthreads();

    unsigned qfh[4][4], qfl[4][4];
    #pragma unroll
    for (int kc = 0; kc < 4; kc++) {
        ldsm_x4(qfh[kc], &SB[arow*KW + kc*8 + acol_q]);
        ldsm_x4(qfl[kc], &SB[QR*KW + arow*KW + kc*8 + acol_q]);
    }

    float acc[8][4] = {};
    float m1 = -INFINITY, m2 = -INFINITY, l1 = 0.f, l2 = 0.f;

    int kr = t >> 5, kk2 = t & 31;          // staging: rows kr + i*8

    for (int kt = 0; kt < SS/64; kt++) {
        __syncthreads();
        size_t tb = kvbase + (size_t)(kt*64) * 32;
        #pragma unroll
        for (int i = 0; i < 8; i++) {
            size_t src = tb + (size_t)(kr + i*8)*32 + kk2;
            int dst = (kr + i*8)*KW + kk2;
            Kh[dst] = g_Kh[src];
            Kl[dst] = g_Kl[src];
            Vh[dst] = g_Vh[src];
            Vl[dst] = g_Vl[src];
        }
        __syncthreads();

        // ---- QK^T ----
        float sacc[8][4] = {};
        #pragma unroll
        for (int kc = 0; kc < 4; kc++) {
            #pragma unroll
            for (int n0p = 0; n0p < 4; n0p++) {
                unsigned bh[4], bl[4];
                int br = (n0p*16 + brow_off)*KW + kc*8 + bcol_q;
                ldsm_x4(bh, &Kh[br]);
                ldsm_x4(bl, &Kl[br]);
                mma16(sacc[2*n0p],   qfh[kc], bh);
                mma16(sacc[2*n0p],   qfh[kc], bl);
                mma16(sacc[2*n0p],   qfl[kc], bh);
                mma16(sacc[2*n0p+1], qfh[kc], bh+2);
                mma16(sacc[2*n0p+1], qfh[kc], bl+2);
                mma16(sacc[2*n0p+1], qfl[kc], bh+2);
            }
        }

        // ---- mask + online softmax, registers ----
        const int* Mr1 = Mp + (size_t)r0 * SS + kt*64;
        const int* Mr2 = Mp + (size_t)(r0 + 8) * SS + kt*64;
        #pragma unroll
        for (int n0 = 0; n0 < 8; n0++) {
            int2 ma = *(const int2*)&Mr1[n0*8 + 2*t4];
            int2 mb = *(const int2*)&Mr2[n0*8 + 2*t4];
            sacc[n0][0] = ma.x ? sacc[n0][0] : -1e9f;
            sacc[n0][1] = ma.y ? sacc[n0][1] : -1e9f;
            sacc[n0][2] = mb.x ? sacc[n0][2] : -1e9f;
            sacc[n0][3] = mb.y ? sacc[n0][3] : -1e9f;
        }
        float mx1 = -INFINITY, mx2 = -INFINITY;
        #pragma unroll
        for (int n0 = 0; n0 < 8; n0++) {
            mx1 = fmaxf(mx1, fmaxf(sacc[n0][0], sacc[n0][1]));
            mx2 = fmaxf(mx2, fmaxf(sacc[n0][2], sacc[n0][3]));
        }
        mx1 = fmaxf(mx1, __shfl_xor_sync(0xffffffffu, mx1, 1));
        mx1 = fmaxf(mx1, __shfl_xor_sync(0xffffffffu, mx1, 2));
        mx2 = fmaxf(mx2, __shfl_xor_sync(0xffffffffu, mx2, 1));
        mx2 = fmaxf(mx2, __shfl_xor_sync(0xffffffffu, mx2, 2));
        float mn1 = fmaxf(m1, mx1), mn2 = fmaxf(m2, mx2);
        float cr1 = __expf(m1 - mn1), cr2 = __expf(m2 - mn2);
        float ls1 = 0.f, ls2 = 0.f;
        #pragma unroll
        for (int n0 = 0; n0 < 8; n0++) {
            float p0 = __expf(sacc[n0][0] - mn1);
            float p1 = __expf(sacc[n0][1] - mn1);
            float p2 = __expf(sacc[n0][2] - mn2);
            float p3 = __expf(sacc[n0][3] - mn2);
            ls1 += p0 + p1; ls2 += p2 + p3;
            sacc[n0][0] = p0; sacc[n0][1] = p1;
            sacc[n0][2] = p2; sacc[n0][3] = p3;
        }
        ls1 += __shfl_xor_sync(0xffffffffu, ls1, 1);
        ls1 += __shfl_xor_sync(0xffffffffu, ls1, 2);
        ls2 += __shfl_xor_sync(0xffffffffu, ls2, 1);
        ls2 += __shfl_xor_sync(0xffffffffu, ls2, 2);
        m1 = mn1; m2 = mn2;
        l1 = l1 * cr1 + ls1;
        l2 = l2 * cr2 + ls2;

        // ---- PV: P frags from sacc; V B-frags via ldmatrix.trans ----
        #pragma unroll
        for (int n0 = 0; n0 < 8; n0++) {
            acc[n0][0] *= cr1; acc[n0][1] *= cr1;
            acc[n0][2] *= cr2; acc[n0][3] *= cr2;
        }
        #pragma unroll
        for (int kc = 0; kc < 4; kc++) {
            unsigned ah[4], al[4];
            split2(sacc[2*kc][0],   sacc[2*kc][1],   ah[0], al[0]);
            split2(sacc[2*kc][2],   sacc[2*kc][3],   ah[1], al[1]);
            split2(sacc[2*kc+1][0], sacc[2*kc+1][1], ah[2], al[2]);
            split2(sacc[2*kc+1][2], sacc[2*kc+1][3], ah[3], al[3]);
            #pragma unroll
            for (int n0p = 0; n0p < 4; n0p++) {
                unsigned bh[4], bl[4];
                int vbr = (kc*16 + vrow_off)*KW + n0p*8 + vcol_q;
                ldsm_x4_trans(bh, &Vh[vbr]);
                ldsm_x4_trans(bl, &Vl[vbr]);
                mma16(acc[2*n0p],   ah, bh);
                mma16(acc[2*n0p],   ah, bl);
                mma16(acc[2*n0p],   al, bh);
                mma16(acc[2*n0p+1], ah, bh+2);
                mma16(acc[2*n0p+1], ah, bl+2);
                mma16(acc[2*n0p+1], al, bh+2);
            }
        }
    }

    float inv1 = 1.f / l1;
    float inv2 = 1.f / l2;
    size_t row1 = (size_t)b*SS + qt*QR + r0;
    #pragma unroll
    for (int n0 = 0; n0 < 8; n0++) {
        int wd = h*32 + n0*4 + t4;
        unsigned hi, lo;
        split2(acc[n0][0]*inv1, acc[n0][1]*inv1, hi, lo);
        g_Ch[row1*384 + wd] = hi; g_Cl[row1*384 + wd] = lo;
        split2(acc[n0][2]*inv2, acc[n0][3]*inv2, hi, lo);
        g_Ch[(row1+8)*384 + wd] = hi; g_Cl[(row1+8)*384 + wd] = lo;
    }
}

// ---------------------------------------------------------------------------
// Output projection: packed C [4096, 384w] @ Wo[768,768] -> f32 out.
// 128x128 tiles, 512 threads (16 warps: 8 M x 2 N-halves). grid=(32, 6).
// ---------------------------------------------------------------------------
__global__ __launch_bounds__(512) void out_gemm_kernel(
    const float* __restrict__ Wo, float* __restrict__ outp)
{
    __shared__ unsigned Ah[128*GW], Al[128*GW];
    __shared__ unsigned Bh[128*GW], Bl[128*GW];

    int bx = blockIdx.x, by = blockIdx.y;
    int t = threadIdx.x, w = t >> 5, l = t & 31;
    int wm = w >> 1;
    int wn = w & 1;
    int t4 = l & 3;
    int g = l >> 2;
    int lj = l >> 3, lr = l & 7;
    int m0 = bx * 128;
    int n0 = by * 128;

    const float* Bbase = Wo + n0;

    float acc[8][4] = {};
    int r0 = 16*wm + g;

    int arow = 16*wm + lr + (lj & 1) * 8;
    int acol_q = (lj >> 1) * 4;
    int brow_off = lr + (lj >> 1) * 8;
    int bcol_q = (lj & 1) * 4;

    int ar = t >> 4, ak2 = t & 15;
    int bn = t & 127, bk2 = t >> 7;

    unsigned pah[4], pal[4];
    float    pb0[4], pb1[4];

    #pragma unroll
    for (int i = 0; i < 4; i++) {
        size_t src = (size_t)(m0 + ar + i*32) * 384 + ak2;
        pah[i] = g_Ch[src];
        pal[i] = g_Cl[src];
    }
    #pragma unroll
    for (int i = 0; i < 4; i++) {
        pb0[i] = Bbase[(size_t)(2*(bk2 + i*4))     * EE + bn];
        pb1[i] = Bbase[(size_t)(2*(bk2 + i*4) + 1) * EE + bn];
    }

    for (int kw = 0; kw < 384; kw += 16) {
        __syncthreads();
        #pragma unroll
        for (int i = 0; i < 4; i++) {
            Ah[(ar + i*32)*GW + ak2] = pah[i];
            Al[(ar + i*32)*GW + ak2] = pal[i];
        }
        #pragma unroll
        for (int i = 0; i < 4; i++)
            split2(pb0[i], pb1[i], Bh[bn*GW + bk2 + i*4], Bl[bn*GW + bk2 + i*4]);
        __syncthreads();

        if (kw + 16 < 384) {
            int knw = kw + 16;
            #pragma unroll
            for (int i = 0; i < 4; i++) {
                size_t src = (size_t)(m0 + ar + i*32) * 384 + knw + ak2;
                pah[i] = g_Ch[src];
                pal[i] = g_Cl[src];
            }
            #pragma unroll
            for (int i = 0; i < 4; i++) {
                pb0[i] = Bbase[(size_t)(2*(knw + bk2 + i*4))     * EE + bn];
                pb1[i] = Bbase[(size_t)(2*(knw + bk2 + i*4) + 1) * EE + bn];
            }
        }

        #pragma unroll
        for (int kc = 0; kc < 2; kc++) {
            unsigned ah[4], al[4];
            ldsm_x4(ah, &Ah[arow*GW + kc*8 + acol_q]);
            ldsm_x4(al, &Al[arow*GW + kc*8 + acol_q]);
            #pragma unroll
            for (int n0p = 0; n0p < 4; n0p++) {
                unsigned bh[4], bl[4];
                int br = (wn*64 + n0p*16 + brow_off)*GW + kc*8 + bcol_q;
                ldsm_x4(bh, &Bh[br]);
                ldsm_x4(bl, &Bl[br]);
                mma16(acc[2*n0p],   ah, bh);
                mma16(acc[2*n0p],   ah, bl);
                mma16(acc[2*n0p],   al, bh);
                mma16(acc[2*n0p+1], ah, bh+2);
                mma16(acc[2*n0p+1], ah, bl+2);
                mma16(acc[2*n0p+1], al, bh+2);
            }
        }
    }

    int rg1 = m0 + r0, rg2 = rg1 + 8;
    #pragma unroll
    for (int nb = 0; nb < 8; nb++) {
        int cn = n0 + wn*64 + nb*8 + 2*t4;
        *(float2*)&outp[(size_t)rg1 * EE + cn] = make_float2(acc[nb][0], acc[nb][1]);
        *(float2*)&outp[(size_t)rg2 * EE + cn] = make_float2(acc[nb][2], acc[nb][3]);
    }
}

// ---------------------------------------------------------------------------
extern "C" void kernel_launch(void* const* d_in, const int* in_sizes, int n_in,
                              void* d_out, int out_size)
{
    const float* q    = (const float*)d_in[0];
    const float* k    = (const float*)d_in[1];
    const float* v    = (const float*)d_in[2];
    const int*   mask = (const int*)  d_in[3];
    const float* Wq   = (const float*)d_in[4];
    const float* Wk   = (const float*)d_in[5];
    const float* Wv   = (const float*)d_in[6];
    const float* W    = (const float*)d_in[7];
    float* out = (float*)d_out;

    qkv_gemm_kernel<<<dim3((BB*SS)/128, (3*EE)/128), 512>>>(q, k, v, Wq, Wk, Wv);
    flash_kernel<<<dim3(SS/QR, HH, BB), 256>>>(mask);
    out_gemm_kernel<<<dim3((BB*SS)/128, EE/128), 512>>>(W, out);
}